// round 3
// baseline (speedup 1.0000x reference)
#include <cuda_runtime.h>
#include <math.h>

// Problem constants
#define NN    4096      // nodes
#define HDIM  32
#define TROLL 200
#define FIN   5
#define KSPLIT 8        // K-split factor for per-step GEMM
#define KCHUNK (NN / KSPLIT)   // 512

// GEMM tile config
#define BM 256
#define BN 64
#define BK 16

// ---------------- device scratch (allocation-free: __device__ globals) ------
__device__ __align__(16) float g_HC[NN * 64];               // [n][0:32]=h, [32:64]=c
__device__ __align__(16) float g_Mpart[(size_t)KSPLIT * NN * 64]; // K-split partials of A@[h|c]
__device__ __align__(16) float g_Xr[(size_t)NN * 1024];     // X rearranged [k][t*5+f], padded to 1024
__device__ __align__(16) float g_C1[(size_t)NN * 1024];     // A @ Xr
__device__ __align__(16) float g_U[101 * 128];              // fused gate matrix
__device__ __align__(16) float g_bias[128];                 // b_ih + b_hh

// ---------------- setup: build fused gate matrix U --------------------------
// gates[n,j] = bias[j] + sum_k v[n,k] * U[k,j]
//   v = [ (A@h)[0:32] | (A@c)[0:32] | h[0:32] | (A@x_t)[0:5] ]
//   U rows 0..31  = Wh @ W_ih^T        (since h_gcn@W_ih^T = (A@h)@(Wh@W_ih^T))
//   U rows 32..63 = Wc @ W_ih^T
//   U rows 64..95 = W_hh^T
//   U rows 96..100= Wx @ W_ih^T
__global__ void setup_kernel(const float* __restrict__ Wx, const float* __restrict__ Wh,
                             const float* __restrict__ Wc, const float* __restrict__ W_ih,
                             const float* __restrict__ W_hh, const float* __restrict__ b_ih,
                             const float* __restrict__ b_hh) {
    const int j = threadIdx.x;  // 0..127 gate column
    __shared__ float sWih[128 * 32];
    for (int i = j; i < 128 * 32; i += 128) sWih[i] = W_ih[i];
    __syncthreads();

    for (int r = 0; r < 32; r++) {
        float s = 0.f;
        for (int m = 0; m < 32; m++) s += Wh[r * 32 + m] * sWih[j * 32 + m];
        g_U[r * 128 + j] = s;
    }
    for (int r = 0; r < 32; r++) {
        float s = 0.f;
        for (int m = 0; m < 32; m++) s += Wc[r * 32 + m] * sWih[j * 32 + m];
        g_U[(32 + r) * 128 + j] = s;
    }
    for (int m = 0; m < 32; m++) g_U[(64 + m) * 128 + j] = W_hh[j * 32 + m];
    for (int f = 0; f < FIN; f++) {
        float s = 0.f;
        for (int m = 0; m < 32; m++) s += Wx[f * 32 + m] * sWih[j * 32 + m];
        g_U[(96 + f) * 128 + j] = s;
    }
    g_bias[j] = b_ih[j] + b_hh[j];
}

__global__ void zero_hc_kernel() {
    int i = blockIdx.x * blockDim.x + threadIdx.x;
    if (i < NN * 64) g_HC[i] = 0.f;
}

// Rearrange X[t][k][f] -> Xr[k][t*5+f], zero-pad cols 1000..1023
__global__ void xr_kernel(const float* __restrict__ X) {
    int idx = blockIdx.x * blockDim.x + threadIdx.x;   // over NN*1024
    int k = idx >> 10;
    int q = idx & 1023;
    float v = 0.f;
    if (q < TROLL * FIN) {
        int t = q / FIN;
        int f = q - t * FIN;
        v = X[(size_t)t * (NN * FIN) + k * FIN + f];
    }
    g_Xr[idx] = v;
}

// ---------------- tiled fp32 GEMM: C[z] = A[rows, krange] @ B -----------------
// Block tile BM x BN over K-chunk, 256 threads, per-thread 8x8 micro-tile.
// smem bytes/FMA = 1.0 (LDS not binding); double-buffered global->smem.
__global__ void __launch_bounds__(256, 1) gemm_tile(
    const float* __restrict__ A, const float* __restrict__ B,
    float* __restrict__ C, int lda, int ldb, int ldc,
    long zstride, int kchunk)
{
    __shared__ float As[2][BK][BM];   // transposed A tile
    __shared__ float Bs[2][BK][BN];

    const int tid = threadIdx.x;
    const int tr = tid >> 3;          // 0..31 (row group)
    const int tc = tid & 7;           // 0..7  (col group)
    const int row0 = blockIdx.x * BM;
    const int col0 = blockIdx.y * BN;
    const int k0 = blockIdx.z * kchunk;

    // A-tile load mapping: lr row-in-64-group, lc k-offset (float4)
    const int lr = tid >> 2;          // 0..63
    const int lc = (tid & 3) * 4;     // 0,4,8,12
    // B-tile load mapping
    const int brow = tid >> 4;        // 0..15
    const int bcol = (tid & 15) * 4;  // 0..60

    const float* Abase = A + (size_t)(row0 + lr) * lda + lc;
    const float* Bbase = B + (size_t)brow * ldb + col0 + bcol;

    float acc[8][8];
    #pragma unroll
    for (int i = 0; i < 8; i++)
        #pragma unroll
        for (int j = 0; j < 8; j++) acc[i][j] = 0.f;

    const int ntiles = kchunk / BK;

    float4 av[4];
    float4 bv;
    // preload tile 0
    {
        const float* Ap = Abase + k0;
        #pragma unroll
        for (int p = 0; p < 4; p++)
            av[p] = *reinterpret_cast<const float4*>(Ap + (size_t)(p * 64) * lda);
        bv = *reinterpret_cast<const float4*>(Bbase + (size_t)k0 * ldb);
    }
    #pragma unroll
    for (int p = 0; p < 4; p++) {
        As[0][lc + 0][p * 64 + lr] = av[p].x;
        As[0][lc + 1][p * 64 + lr] = av[p].y;
        As[0][lc + 2][p * 64 + lr] = av[p].z;
        As[0][lc + 3][p * 64 + lr] = av[p].w;
    }
    *reinterpret_cast<float4*>(&Bs[0][brow][bcol]) = bv;
    __syncthreads();

    int buf = 0;
    for (int kt = 0; kt < ntiles; kt++) {
        const bool has_next = (kt + 1 < ntiles);
        if (has_next) {
            const int kk = k0 + (kt + 1) * BK;
            const float* Ap = Abase + kk;
            #pragma unroll
            for (int p = 0; p < 4; p++)
                av[p] = *reinterpret_cast<const float4*>(Ap + (size_t)(p * 64) * lda);
            bv = *reinterpret_cast<const float4*>(Bbase + (size_t)kk * ldb);
        }
        #pragma unroll
        for (int k = 0; k < BK; k++) {
            float4 a0 = *reinterpret_cast<const float4*>(&As[buf][k][tr * 8]);
            float4 a1 = *reinterpret_cast<const float4*>(&As[buf][k][tr * 8 + 4]);
            float4 b0 = *reinterpret_cast<const float4*>(&Bs[buf][k][tc * 8]);
            float4 b1 = *reinterpret_cast<const float4*>(&Bs[buf][k][tc * 8 + 4]);
            float a[8] = {a0.x, a0.y, a0.z, a0.w, a1.x, a1.y, a1.z, a1.w};
            float b[8] = {b0.x, b0.y, b0.z, b0.w, b1.x, b1.y, b1.z, b1.w};
            #pragma unroll
            for (int i = 0; i < 8; i++)
                #pragma unroll
                for (int j = 0; j < 8; j++)
                    acc[i][j] += a[i] * b[j];
        }
        if (has_next) {
            const int nb = buf ^ 1;
            #pragma unroll
            for (int p = 0; p < 4; p++) {
                As[nb][lc + 0][p * 64 + lr] = av[p].x;
                As[nb][lc + 1][p * 64 + lr] = av[p].y;
                As[nb][lc + 2][p * 64 + lr] = av[p].z;
                As[nb][lc + 3][p * 64 + lr] = av[p].w;
            }
            *reinterpret_cast<float4*>(&Bs[nb][brow][bcol]) = bv;
        }
        __syncthreads();
        buf ^= 1;
    }

    float* Cp = C + (size_t)blockIdx.z * zstride + (size_t)(row0 + tr * 8) * ldc + col0 + tc * 8;
    #pragma unroll
    for (int i = 0; i < 8; i++) {
        *reinterpret_cast<float4*>(Cp + (size_t)i * ldc) =
            make_float4(acc[i][0], acc[i][1], acc[i][2], acc[i][3]);
        *reinterpret_cast<float4*>(Cp + (size_t)i * ldc + 4) =
            make_float4(acc[i][4], acc[i][5], acc[i][6], acc[i][7]);
    }
}

// ---------------- gates + LSTM update ---------------------------------------
// Reduces the KSPLIT partials, applies U, LSTM nonlinearity, writes new h,c.
__global__ void __launch_bounds__(128) gates_kernel(int t) {
    const int tid = threadIdx.x;      // gate column j = tid
    __shared__ float sv[101];
    __shared__ float sg[128];

    float uj[101];                    // U column j, register-resident
    #pragma unroll
    for (int k = 0; k < 101; k++) uj[k] = g_U[k * 128 + tid];
    const float bj = g_bias[tid];

    const int row_base = blockIdx.x * 32;
    for (int r = 0; r < 32; r++) {
        const int n = row_base + r;
        if (tid < 64) {               // reduce A@[h|c] partials
            float s = 0.f;
            #pragma unroll
            for (int z = 0; z < KSPLIT; z++)
                s += g_Mpart[((size_t)z * NN + n) * 64 + tid];
            sv[tid] = s;
        } else if (tid < 96) {        // old h
            sv[tid] = g_HC[n * 64 + (tid - 64)];
        } else if (tid < 101) {       // (A@x_t) row
            sv[tid] = g_C1[(size_t)n * 1024 + t * FIN + (tid - 96)];
        }
        __syncthreads();

        float g = bj;
        #pragma unroll
        for (int k = 0; k < 101; k++) g += sv[k] * uj[k];
        sg[tid] = g;
        __syncthreads();

        if (tid < 32) {
            float ii = 1.f / (1.f + expf(-sg[tid]));
            float ff = 1.f / (1.f + expf(-sg[32 + tid]));
            float gg = tanhf(sg[64 + tid]);
            float oo = 1.f / (1.f + expf(-sg[96 + tid]));
            float c_old = g_HC[n * 64 + 32 + tid];
            float c_new = ff * c_old + ii * gg;
            g_HC[n * 64 + tid] = oo * tanhf(c_new);
            g_HC[n * 64 + 32 + tid] = c_new;
        }
        __syncthreads();
    }
}

// ---------------- final projection ------------------------------------------
__global__ void final_kernel(const float* __restrict__ W_fc,
                             const float* __restrict__ b_fc,
                             float* __restrict__ out) {
    int n = blockIdx.x * blockDim.x + threadIdx.x;
    if (n >= NN) return;
    float s = b_fc[0];
    #pragma unroll
    for (int u = 0; u < HDIM; u++) s += g_HC[n * 64 + u] * W_fc[u];
    out[n] = s;
}

// ---------------- launch ------------------------------------------------------
extern "C" void kernel_launch(void* const* d_in, const int* in_sizes, int n_in,
                              void* d_out, int out_size) {
    const float* X    = (const float*)d_in[0];
    const float* A    = (const float*)d_in[1];
    const float* Wx   = (const float*)d_in[2];
    const float* Wh   = (const float*)d_in[3];
    const float* Wc   = (const float*)d_in[4];
    const float* W_ih = (const float*)d_in[5];
    const float* W_hh = (const float*)d_in[6];
    const float* b_ih = (const float*)d_in[7];
    const float* b_hh = (const float*)d_in[8];
    const float* W_fc = (const float*)d_in[9];
    const float* b_fc = (const float*)d_in[10];

    float *dXr, *dC1, *dHC, *dMp;
    cudaGetSymbolAddress((void**)&dXr, g_Xr);
    cudaGetSymbolAddress((void**)&dC1, g_C1);
    cudaGetSymbolAddress((void**)&dHC, g_HC);
    cudaGetSymbolAddress((void**)&dMp, g_Mpart);

    setup_kernel<<<1, 128>>>(Wx, Wh, Wc, W_ih, W_hh, b_ih, b_hh);
    zero_hc_kernel<<<(NN * 64 + 255) / 256, 256>>>();
    xr_kernel<<<(NN * 1024) / 256, 256>>>(X);

    // one-time precompute: C1 = A @ Xr  ([4096x4096]@[4096x1024])
    gemm_tile<<<dim3(NN / BM, 1024 / BN, 1), 256>>>(A, dXr, dC1,
                                                    NN, 1024, 1024, 0L, NN);

    for (int t = 0; t < TROLL; t++) {
        // M = A @ [h|c], K-split into 8 partials (128 blocks = full wave)
        gemm_tile<<<dim3(NN / BM, 1, KSPLIT), 256>>>(A, dHC, dMp,
                                                     NN, 64, 64,
                                                     (long)NN * 64, KCHUNK);
        gates_kernel<<<NN / 32, 128>>>(t);
    }

    final_kernel<<<NN / 256, 256>>>(W_fc, b_fc, (float*)d_out);
}

// round 4
// speedup vs baseline: 1.1707x; 1.1707x over previous
#include <cuda_runtime.h>
#include <math.h>

// Problem constants
#define NN    4096      // nodes
#define HDIM  32
#define TROLL 200
#define FIN   5
#define KSPLIT 8        // K-split factor for per-step GEMM
#define KCHUNK (NN / KSPLIT)   // 512

// GEMM tile config
#define BM 256
#define BN 64
#define BK 16

typedef unsigned long long u64;

__device__ __forceinline__ u64 pack2(float x, float y) {
    u64 r;
    asm("mov.b64 %0, {%1, %2};" : "=l"(r) : "f"(x), "f"(y));
    return r;
}
__device__ __forceinline__ void unpack2(u64 v, float& x, float& y) {
    asm("mov.b64 {%0, %1}, %2;" : "=f"(x), "=f"(y) : "l"(v));
}
__device__ __forceinline__ void ffma2(u64& d, u64 a, u64 b) {
    asm("fma.rn.f32x2 %0, %1, %2, %0;" : "+l"(d) : "l"(a), "l"(b));
}

// ---------------- device scratch (allocation-free: __device__ globals) ------
__device__ __align__(16) float g_HC[NN * 64];               // [n][0:32]=h, [32:64]=c
__device__ __align__(16) float g_Mpart[(size_t)KSPLIT * NN * 64]; // K-split partials of A@[h|c]
__device__ __align__(16) float g_Xr[(size_t)NN * 1024];     // X rearranged [k][t*5+f], padded to 1024
__device__ __align__(16) float g_C1[(size_t)NN * 1024];     // A @ Xr
__device__ __align__(16) float g_U[101 * 128];              // fused gate matrix
__device__ __align__(16) float g_bias[128];                 // b_ih + b_hh

// ---------------- setup: build fused gate matrix U --------------------------
// gates[n,j] = bias[j] + sum_k v[n,k] * U[k,j]
//   v = [ (A@h)[0:32] | (A@c)[0:32] | h[0:32] | (A@x_t)[0:5] ]
__global__ void setup_kernel(const float* __restrict__ Wx, const float* __restrict__ Wh,
                             const float* __restrict__ Wc, const float* __restrict__ W_ih,
                             const float* __restrict__ W_hh, const float* __restrict__ b_ih,
                             const float* __restrict__ b_hh) {
    const int j = threadIdx.x;  // 0..127 gate column
    __shared__ float sWih[128 * 32];
    for (int i = j; i < 128 * 32; i += 128) sWih[i] = W_ih[i];
    __syncthreads();

    for (int r = 0; r < 32; r++) {
        float s = 0.f;
        for (int m = 0; m < 32; m++) s += Wh[r * 32 + m] * sWih[j * 32 + m];
        g_U[r * 128 + j] = s;
    }
    for (int r = 0; r < 32; r++) {
        float s = 0.f;
        for (int m = 0; m < 32; m++) s += Wc[r * 32 + m] * sWih[j * 32 + m];
        g_U[(32 + r) * 128 + j] = s;
    }
    for (int m = 0; m < 32; m++) g_U[(64 + m) * 128 + j] = W_hh[j * 32 + m];
    for (int f = 0; f < FIN; f++) {
        float s = 0.f;
        for (int m = 0; m < 32; m++) s += Wx[f * 32 + m] * sWih[j * 32 + m];
        g_U[(96 + f) * 128 + j] = s;
    }
    g_bias[j] = b_ih[j] + b_hh[j];
}

__global__ void zero_hc_kernel() {
    int i = blockIdx.x * blockDim.x + threadIdx.x;
    if (i < NN * 64) g_HC[i] = 0.f;
}

// Rearrange X[t][k][f] -> Xr[k][t*5+f], zero-pad cols 1000..1023
__global__ void xr_kernel(const float* __restrict__ X) {
    int idx = blockIdx.x * blockDim.x + threadIdx.x;   // over NN*1024
    int k = idx >> 10;
    int q = idx & 1023;
    float v = 0.f;
    if (q < TROLL * FIN) {
        int t = q / FIN;
        int f = q - t * FIN;
        v = X[(size_t)t * (NN * FIN) + k * FIN + f];
    }
    g_Xr[idx] = v;
}

// ---------------- tiled fp32 GEMM with packed FFMA2 --------------------------
// C[z] = A[rows, krange] @ B. Block tile BM x BN over K-chunk, 256 threads,
// per-thread 8x8 micro-tile computed as 4x8 f32x2 pairs (paired along M).
// A-pairs come directly from the transposed As tile (ulonglong2 loads);
// b values are broadcast-packed on the ALU pipe (does not contend with fma).
__global__ void __launch_bounds__(256, 1) gemm_tile(
    const float* __restrict__ A, const float* __restrict__ B,
    float* __restrict__ C, int lda, int ldb, int ldc,
    long zstride, int kchunk)
{
    __shared__ __align__(16) float As[2][BK][BM];   // transposed A tile
    __shared__ __align__(16) float Bs[2][BK][BN];

    const int tid = threadIdx.x;
    const int tr = tid >> 3;          // 0..31 (row group)
    const int tc = tid & 7;           // 0..7  (col group)
    const int row0 = blockIdx.x * BM;
    const int col0 = blockIdx.y * BN;
    const int k0 = blockIdx.z * kchunk;

    // A-tile load mapping
    const int lr = tid >> 2;          // 0..63
    const int lc = (tid & 3) * 4;     // 0,4,8,12
    // B-tile load mapping
    const int brow = tid >> 4;        // 0..15
    const int bcol = (tid & 15) * 4;  // 0..60

    const float* Abase = A + (size_t)(row0 + lr) * lda + lc;
    const float* Bbase = B + (size_t)brow * ldb + col0 + bcol;

    u64 acc[4][8];                    // acc[ii][j] = {C[2ii][j], C[2ii+1][j]}
    #pragma unroll
    for (int i = 0; i < 4; i++)
        #pragma unroll
        for (int j = 0; j < 8; j++) acc[i][j] = 0ull;

    const int ntiles = kchunk / BK;

    float4 av[4];
    float4 bv;
    // preload tile 0
    {
        const float* Ap = Abase + k0;
        #pragma unroll
        for (int p = 0; p < 4; p++)
            av[p] = *reinterpret_cast<const float4*>(Ap + (size_t)(p * 64) * lda);
        bv = *reinterpret_cast<const float4*>(Bbase + (size_t)k0 * ldb);
    }
    #pragma unroll
    for (int p = 0; p < 4; p++) {
        As[0][lc + 0][p * 64 + lr] = av[p].x;
        As[0][lc + 1][p * 64 + lr] = av[p].y;
        As[0][lc + 2][p * 64 + lr] = av[p].z;
        As[0][lc + 3][p * 64 + lr] = av[p].w;
    }
    *reinterpret_cast<float4*>(&Bs[0][brow][bcol]) = bv;
    __syncthreads();

    int buf = 0;
    for (int kt = 0; kt < ntiles; kt++) {
        const bool has_next = (kt + 1 < ntiles);
        if (has_next) {
            const int kk = k0 + (kt + 1) * BK;
            const float* Ap = Abase + kk;
            #pragma unroll
            for (int p = 0; p < 4; p++)
                av[p] = *reinterpret_cast<const float4*>(Ap + (size_t)(p * 64) * lda);
            bv = *reinterpret_cast<const float4*>(Bbase + (size_t)kk * ldb);
        }
        #pragma unroll
        for (int k = 0; k < BK; k++) {
            ulonglong2 A0 = *reinterpret_cast<const ulonglong2*>(&As[buf][k][tr * 8]);
            ulonglong2 A1 = *reinterpret_cast<const ulonglong2*>(&As[buf][k][tr * 8 + 4]);
            float4 b0 = *reinterpret_cast<const float4*>(&Bs[buf][k][tc * 8]);
            float4 b1 = *reinterpret_cast<const float4*>(&Bs[buf][k][tc * 8 + 4]);
            u64 ar[4];
            ar[0] = A0.x; ar[1] = A0.y; ar[2] = A1.x; ar[3] = A1.y;
            u64 bb[8];
            bb[0] = pack2(b0.x, b0.x);
            bb[1] = pack2(b0.y, b0.y);
            bb[2] = pack2(b0.z, b0.z);
            bb[3] = pack2(b0.w, b0.w);
            bb[4] = pack2(b1.x, b1.x);
            bb[5] = pack2(b1.y, b1.y);
            bb[6] = pack2(b1.z, b1.z);
            bb[7] = pack2(b1.w, b1.w);
            #pragma unroll
            for (int ii = 0; ii < 4; ii++)
                #pragma unroll
                for (int j = 0; j < 8; j++)
                    ffma2(acc[ii][j], ar[ii], bb[j]);
        }
        if (has_next) {
            const int nb = buf ^ 1;
            #pragma unroll
            for (int p = 0; p < 4; p++) {
                As[nb][lc + 0][p * 64 + lr] = av[p].x;
                As[nb][lc + 1][p * 64 + lr] = av[p].y;
                As[nb][lc + 2][p * 64 + lr] = av[p].z;
                As[nb][lc + 3][p * 64 + lr] = av[p].w;
            }
            *reinterpret_cast<float4*>(&Bs[nb][brow][bcol]) = bv;
        }
        __syncthreads();
        buf ^= 1;
    }

    float* Cp = C + (size_t)blockIdx.z * zstride + (size_t)(row0 + tr * 8) * ldc + col0 + tc * 8;
    #pragma unroll
    for (int ii = 0; ii < 4; ii++) {
        float lo[8], hi[8];
        #pragma unroll
        for (int j = 0; j < 8; j++) unpack2(acc[ii][j], lo[j], hi[j]);
        float* r0 = Cp + (size_t)(2 * ii) * ldc;
        float* r1 = Cp + (size_t)(2 * ii + 1) * ldc;
        *reinterpret_cast<float4*>(r0)     = make_float4(lo[0], lo[1], lo[2], lo[3]);
        *reinterpret_cast<float4*>(r0 + 4) = make_float4(lo[4], lo[5], lo[6], lo[7]);
        *reinterpret_cast<float4*>(r1)     = make_float4(hi[0], hi[1], hi[2], hi[3]);
        *reinterpret_cast<float4*>(r1 + 4) = make_float4(hi[4], hi[5], hi[6], hi[7]);
    }
}

// ---------------- gates + LSTM update ---------------------------------------
// Reduces the KSPLIT partials, applies U, LSTM nonlinearity, writes new h,c.
#define GROWS 16
__global__ void __launch_bounds__(128) gates_kernel(int t) {
    const int tid = threadIdx.x;      // gate column j = tid
    __shared__ float sv[101];
    __shared__ float sg[128];

    float uj[101];                    // U column j, register-resident
    #pragma unroll
    for (int k = 0; k < 101; k++) uj[k] = g_U[k * 128 + tid];
    const float bj = g_bias[tid];

    const int row_base = blockIdx.x * GROWS;
    for (int r = 0; r < GROWS; r++) {
        const int n = row_base + r;
        if (tid < 64) {               // reduce A@[h|c] partials
            float s = 0.f;
            #pragma unroll
            for (int z = 0; z < KSPLIT; z++)
                s += g_Mpart[((size_t)z * NN + n) * 64 + tid];
            sv[tid] = s;
        } else if (tid < 96) {        // old h
            sv[tid] = g_HC[n * 64 + (tid - 64)];
        } else if (tid < 101) {       // (A@x_t) row
            sv[tid] = g_C1[(size_t)n * 1024 + t * FIN + (tid - 96)];
        }
        __syncthreads();

        float g = bj;
        #pragma unroll
        for (int k = 0; k < 101; k++) g += sv[k] * uj[k];
        sg[tid] = g;
        __syncthreads();

        if (tid < 32) {
            float ii = 1.f / (1.f + expf(-sg[tid]));
            float ff = 1.f / (1.f + expf(-sg[32 + tid]));
            float gg = tanhf(sg[64 + tid]);
            float oo = 1.f / (1.f + expf(-sg[96 + tid]));
            float c_old = g_HC[n * 64 + 32 + tid];
            float c_new = ff * c_old + ii * gg;
            g_HC[n * 64 + tid] = oo * tanhf(c_new);
            g_HC[n * 64 + 32 + tid] = c_new;
        }
        __syncthreads();
    }
}

// ---------------- final projection ------------------------------------------
__global__ void final_kernel(const float* __restrict__ W_fc,
                             const float* __restrict__ b_fc,
                             float* __restrict__ out) {
    int n = blockIdx.x * blockDim.x + threadIdx.x;
    if (n >= NN) return;
    float s = b_fc[0];
    #pragma unroll
    for (int u = 0; u < HDIM; u++) s += g_HC[n * 64 + u] * W_fc[u];
    out[n] = s;
}

// ---------------- launch ------------------------------------------------------
extern "C" void kernel_launch(void* const* d_in, const int* in_sizes, int n_in,
                              void* d_out, int out_size) {
    const float* X    = (const float*)d_in[0];
    const float* A    = (const float*)d_in[1];
    const float* Wx   = (const float*)d_in[2];
    const float* Wh   = (const float*)d_in[3];
    const float* Wc   = (const float*)d_in[4];
    const float* W_ih = (const float*)d_in[5];
    const float* W_hh = (const float*)d_in[6];
    const float* b_ih = (const float*)d_in[7];
    const float* b_hh = (const float*)d_in[8];
    const float* W_fc = (const float*)d_in[9];
    const float* b_fc = (const float*)d_in[10];

    float *dXr, *dC1, *dHC, *dMp;
    cudaGetSymbolAddress((void**)&dXr, g_Xr);
    cudaGetSymbolAddress((void**)&dC1, g_C1);
    cudaGetSymbolAddress((void**)&dHC, g_HC);
    cudaGetSymbolAddress((void**)&dMp, g_Mpart);

    setup_kernel<<<1, 128>>>(Wx, Wh, Wc, W_ih, W_hh, b_ih, b_hh);
    zero_hc_kernel<<<(NN * 64 + 255) / 256, 256>>>();
    xr_kernel<<<(NN * 1024) / 256, 256>>>(X);

    // one-time precompute: C1 = A @ Xr  ([4096x4096]@[4096x1024])
    gemm_tile<<<dim3(NN / BM, 1024 / BN, 1), 256>>>(A, dXr, dC1,
                                                    NN, 1024, 1024, 0L, NN);

    for (int t = 0; t < TROLL; t++) {
        // M = A @ [h|c], K-split into 8 partials (128 blocks ~ one full wave)
        gemm_tile<<<dim3(NN / BM, 1, KSPLIT), 256>>>(A, dHC, dMp,
                                                     NN, 64, 64,
                                                     (long)NN * 64, KCHUNK);
        gates_kernel<<<NN / GROWS, 128>>>(t);
    }

    final_kernel<<<NN / 256, 256>>>(W_fc, b_fc, (float*)d_out);
}